// round 7
// baseline (speedup 1.0000x reference)
#include <cuda_runtime.h>
#include <stdint.h>

#define NN    2048
#define BSZ   16
#define NEGINF (-1e30f)

// ---------------- device scratch (static globals; no runtime allocation) ----
static __device__ float g_at[BSZ];
static __device__ float g_sc[BSZ];
static __device__ float g_csx[BSZ * 32];
static __device__ float g_csy[BSZ * 32];
static __device__ float g_biasB[BSZ * 64];
static __device__ __align__(16) float g_Wb[BSZ * 96 * 64];
static __device__ __align__(16) float g_Wn[NN * 96 * 64];     // 50.3 MB
static __device__ float g_unif[BSZ * NN];
static __device__ float g_w[BSZ * NN * 10];
static __device__ int   g_sidx[BSZ * NN * 10];
static __device__ __align__(16) float g_y1[BSZ * NN * 32];
static __device__ __align__(16) float g_y2[BSZ * NN * 32];

// ---------------- bit-exact threefry-2x32-20, key = (0, 42) -----------------
__device__ __forceinline__ void threefry_0_42(uint32_t x0, uint32_t x1,
                                              uint32_t& o0, uint32_t& o1) {
    const uint32_t ks0 = 0u, ks1 = 42u, ks2 = 0x1BD11BF0u; // 0^42^0x1BD11BDA
    x0 += ks0; x1 += ks1;
#define TF_R(r) { x0 += x1; x1 = (x1 << (r)) | (x1 >> (32 - (r))); x1 ^= x0; }
    TF_R(13) TF_R(15) TF_R(26) TF_R(6)   x0 += ks1; x1 += ks2 + 1u;
    TF_R(17) TF_R(29) TF_R(16) TF_R(24)  x0 += ks2; x1 += ks0 + 2u;
    TF_R(13) TF_R(15) TF_R(26) TF_R(6)   x0 += ks0; x1 += ks1 + 3u;
    TF_R(17) TF_R(29) TF_R(16) TF_R(24)  x0 += ks1; x1 += ks2 + 4u;
    TF_R(13) TF_R(15) TF_R(26) TF_R(6)   x0 += ks2; x1 += ks0 + 5u;
#undef TF_R
    o0 = x0; o1 = x1;
}

// Partitionable threefry, xor-combine hypothesis: counter = (hi,lo) = (0,e),
// 32-bit output = bits1 ^ bits2. JAX uniform: bitcast((bits>>9)|0x3f800000)-1.
__device__ __forceinline__ float jax_noise(uint32_t e) {
    uint32_t o0, o1;
    threefry_0_42(0u, e, o0, o1);
    uint32_t bits = o0 ^ o1;
    float u = __uint_as_float((bits >> 9) | 0x3f800000u) - 1.0f;
    return __fmul_rn(u, 0.01f);
}

// ---------------- K1: per-batch scalars, biasB, Wb ---------------------------
__global__ void k_prep(const float* __restrict__ t, const float* __restrict__ nt,
                       const float* __restrict__ p, const float* __restrict__ wp,
                       const float* __restrict__ bp) {
    int b = blockIdx.x, tid = threadIdx.x;
    __shared__ float snt[8];
    if (tid < 8) snt[tid] = nt[b * 8 + tid];
    __syncthreads();
    if (tid == 0) {
        float at = 0.f;
        for (int d = 0; d < 8; d++) at += snt[d] * t[b * 8 + d];
        g_at[b] = at;
        float pv = p[b];
        g_sc[b] = 1.f + 0.3f * (1.f / (1.f + expf(-pv)));
    }
    float acc = 0.f;
#pragma unroll
    for (int d = 0; d < 8; d++) acc += snt[d] * bp[(10 + d) * 64 + tid];
    g_biasB[b * 64 + tid] = acc;
    for (int ki = 0; ki < 96; ki++) {
        float a2 = 0.f;
#pragma unroll
        for (int d = 0; d < 8; d++) a2 += snt[d] * wp[(10 + d) * 6144 + ki * 64 + tid];
        g_Wb[b * 6144 + ki * 64 + tid] = a2;
    }
}

// ---------------- K2/K6: column sums over nodes ------------------------------
__global__ void k_colsum(const float* __restrict__ src, float* __restrict__ dst) {
    int b = blockIdx.x, tid = threadIdx.x;
    int c = tid & 31, r0 = tid >> 5;
    float acc = 0.f;
    for (int n = r0; n < NN; n += 8) acc += src[(b * NN + n) * 32 + c];
    __shared__ float sm[256];
    sm[tid] = acc;
    __syncthreads();
    if (tid < 32) {
        float a = sm[tid];
#pragma unroll
        for (int g = 1; g < 8; g++) a += sm[g * 32 + tid];
        dst[b * 32 + tid] = a;
    }
}

// ---------------- K3: Wn = node_emb @ wp[:10]  (skinny GEMM) -----------------
__global__ __launch_bounds__(256) void k_wn(const float* __restrict__ ne,
                                            const float* __restrict__ wp) {
    int tid = threadIdx.x;
    int col = blockIdx.y * 256 + tid;          // 0..6143
    int n0 = blockIdx.x * 16;
    __shared__ float wps[10 * 256];
    __shared__ float nes[16 * 10];
#pragma unroll
    for (int d = 0; d < 10; d++) wps[d * 256 + tid] = wp[d * 6144 + col];
    if (tid < 160) nes[tid] = ne[n0 * 10 + tid];
    __syncthreads();
    for (int nn = 0; nn < 16; nn++) {
        float acc = 0.f;
#pragma unroll
        for (int d = 0; d < 10; d++) acc += nes[nn * 10 + d] * wps[d * 256 + tid];
        g_Wn[(n0 + nn) * 6144 + col] = acc;
    }
}

// ---------------- K4: per-row candidates + per-batch topk/softmax ------------
__global__ __launch_bounds__(256) void k_select(const float* __restrict__ ne) {
    int i = blockIdx.x, tid = threadIdx.x;
    int lane = tid & 31, w = tid >> 5;
    __shared__ float s_a[NN];
    __shared__ float nei[10];
    __shared__ float s_cv[16];
    __shared__ int   s_ci[16];
    __shared__ float s_rv[8];
    __shared__ int   s_ri[8];

    if (tid < 10) nei[tid] = ne[i * 10 + tid];
    __syncthreads();
    for (int j = tid; j < NN; j += 256) {
        const float* nj = ne + j * 10;
        float acc = 0.f;
#pragma unroll
        for (int d = 0; d < 10; d++) acc += nei[d] * nj[d];
        s_a[j] = acc;
    }
    __syncthreads();

    // 16 rounds of block argmax (tie -> lower index)
    for (int r = 0; r < 16; r++) {
        float bv = NEGINF; int bi = 0x7fffffff;
        for (int j = tid; j < NN; j += 256) {
            float v = s_a[j];
            if (v > bv) { bv = v; bi = j; }
        }
#pragma unroll
        for (int off = 16; off; off >>= 1) {
            float ov = __shfl_down_sync(0xffffffffu, bv, off);
            int   oi = __shfl_down_sync(0xffffffffu, bi, off);
            if (ov > bv || (ov == bv && oi < bi)) { bv = ov; bi = oi; }
        }
        if (lane == 0) { s_rv[w] = bv; s_ri[w] = bi; }
        __syncthreads();
        if (tid == 0) {
            for (int g = 1; g < 8; g++)
                if (s_rv[g] > bv || (s_rv[g] == bv && s_ri[g] < bi)) { bv = s_rv[g]; bi = s_ri[g]; }
            s_cv[r] = bv; s_ci[r] = bi; s_a[bi] = NEGINF;
        }
        __syncthreads();
    }

    // per-batch: warp w handles batches w and w+8
    for (int bb = 0; bb < 2; bb++) {
        int b = w + bb * 8;
        float s = g_sc[b], at = g_at[b];
        float myv = 0.f, key = NEGINF;
        int cj = -1;
        if (lane < 16) {
            cj = s_ci[lane];
            float pre = s * (s_cv[lane] + at);
            myv = pre > 0.f ? pre : 0.f;
            uint32_t e = (uint32_t)b * 4194304u + (uint32_t)i * 2048u + (uint32_t)cj;
            key = __fadd_rn(myv, jax_noise(e));
        }
        // top-10 of 16 by key
        float kwork = key;
        bool sel = false;
#pragma unroll
        for (int r = 0; r < 10; r++) {
            float bv = kwork; int bl = lane;
#pragma unroll
            for (int off = 16; off; off >>= 1) {
                float ov = __shfl_down_sync(0xffffffffu, bv, off);
                int   ol = __shfl_down_sync(0xffffffffu, bl, off);
                if (ov > bv) { bv = ov; bl = ol; }
            }
            bl = __shfl_sync(0xffffffffu, bl, 0);
            if (lane == bl) { sel = true; kwork = NEGINF; }
        }
        // softmax over 2048 entries: 10 selected values, 2038 zeros
        float mv = sel ? myv : NEGINF;
#pragma unroll
        for (int off = 16; off; off >>= 1)
            mv = fmaxf(mv, __shfl_down_sync(0xffffffffu, mv, off));
        float m = __shfl_sync(0xffffffffu, mv, 0);
        float se = sel ? expf(myv - m) : 0.f;
        float ss = se;
#pragma unroll
        for (int off = 16; off; off >>= 1)
            ss += __shfl_down_sync(0xffffffffu, ss, off);
        ss = __shfl_sync(0xffffffffu, ss, 0);
        float eu = expf(-m);
        float Z = ss + 2038.f * eu;
        float unif = eu / Z;
        unsigned mask = __ballot_sync(0xffffffffu, sel);
        if (sel) {
            int pos = __popc(mask & ((1u << lane) - 1u));
            int base = (b * NN + i) * 10 + pos;
            g_sidx[base] = cj;
            g_w[base] = se / Z - unif;
        }
        if (lane == 0) g_unif[b * NN + i] = unif;
    }
}

// ---------------- K5/K7: y = A @ src (uniform + sparse); pass2: y=2y-x -------
__global__ __launch_bounds__(256) void k_spmv(const float* __restrict__ src,
                                              const float* __restrict__ cs,
                                              const float* __restrict__ x,
                                              float* __restrict__ dst, int pass2) {
    int lane = threadIdx.x & 31, w = threadIdx.x >> 5;
    int r = blockIdx.x * 8 + w;                  // r = b*2048 + n
    int b = r >> 11;
    float acc = g_unif[r] * cs[b * 32 + lane];
    const int*   id = g_sidx + r * 10;
    const float* ww = g_w + r * 10;
#pragma unroll
    for (int tt = 0; tt < 10; tt++)
        acc += ww[tt] * src[(b * NN + id[tt]) * 32 + lane];
    if (pass2) acc = 2.f * acc - x[r * 32 + lane];
    dst[r * 32 + lane] = acc;
}

// ---------------- K8: per-node term + biases (writes out) --------------------
__global__ __launch_bounds__(128) void k_out1(const float* __restrict__ x,
                                              const float* __restrict__ y1,
                                              const float* __restrict__ y2,
                                              const float* __restrict__ ne,
                                              const float* __restrict__ bp,
                                              float* __restrict__ out) {
    int n = blockIdx.x, tid = threadIdx.x;
    __shared__ float sW[6144];
    __shared__ float sx[16 * 96];
    __shared__ float sbp[640];
    __shared__ float snerow[10];
    for (int m = tid; m < 6144; m += 128) sW[m] = g_Wn[n * 6144 + m];
    for (int m = tid; m < 1536; m += 128) {
        int b = m / 96, k = m - b * 96;
        const float* src = (k < 32) ? x : (k < 64) ? y1 : y2;
        sx[m] = src[(b * NN + n) * 32 + (k & 31)];
    }
    for (int m = tid; m < 640; m += 128) sbp[m] = bp[m];
    if (tid < 10) snerow[tid] = ne[n * 10 + tid];
    __syncthreads();
    int o = tid & 63, g = tid >> 6;
    float acc[8] = {0, 0, 0, 0, 0, 0, 0, 0};
    for (int k = 0; k < 96; k++) {
        float wv = sW[k * 64 + o];
#pragma unroll
        for (int q = 0; q < 8; q++) acc[q] += sx[(g + 2 * q) * 96 + k] * wv;
    }
    float bn = 0.f;
#pragma unroll
    for (int d = 0; d < 10; d++) bn += snerow[d] * sbp[d * 64 + o];
#pragma unroll
    for (int q = 0; q < 8; q++) {
        int b = g + 2 * q;
        out[((b * NN) + n) * 64 + o] = acc[q] + bn + g_biasB[b * 64 + o];
    }
}

// ---------------- K9: per-batch GEMM term, accumulates into out --------------
__global__ __launch_bounds__(256) void k_out2(const float* __restrict__ x,
                                              const float* __restrict__ y1,
                                              const float* __restrict__ y2,
                                              float* __restrict__ out) {
    int n0 = blockIdx.x * 64, b = blockIdx.y, tid = threadIdx.x;
    __shared__ float sWb[48 * 64];
    __shared__ float sxg[64 * 97];
    {
        const float* srcs[3] = {x, y1, y2};
#pragma unroll
        for (int a = 0; a < 3; a++) {
            const float* s = srcs[a];
            for (int m = tid; m < 2048; m += 256) {
                int rr = m >> 5, c = m & 31;
                sxg[rr * 97 + a * 32 + c] = s[(b * NN + n0 + rr) * 32 + c];
            }
        }
    }
    int o0 = (tid & 15) * 4, tn = tid >> 4;
    float acc[4][4];
#pragma unroll
    for (int rr = 0; rr < 4; rr++)
#pragma unroll
        for (int oo = 0; oo < 4; oo++) acc[rr][oo] = 0.f;

    for (int kc = 0; kc < 2; kc++) {
        __syncthreads();
        for (int m = tid; m < 3072; m += 256)
            sWb[m] = g_Wb[b * 6144 + kc * 3072 + m];
        __syncthreads();
        for (int k = 0; k < 48; k++) {
            float4 wv = *(const float4*)&sWb[k * 64 + o0];
#pragma unroll
            for (int rr = 0; rr < 4; rr++) {
                float xv = sxg[(tn + 16 * rr) * 97 + kc * 48 + k];
                acc[rr][0] += xv * wv.x; acc[rr][1] += xv * wv.y;
                acc[rr][2] += xv * wv.z; acc[rr][3] += xv * wv.w;
            }
        }
    }
#pragma unroll
    for (int rr = 0; rr < 4; rr++) {
        int row = tn + 16 * rr;
        float4* op = (float4*)&out[((b * NN) + (n0 + row)) * 64 + o0];
        float4 cur = *op;
        cur.x += acc[rr][0]; cur.y += acc[rr][1];
        cur.z += acc[rr][2]; cur.w += acc[rr][3];
        *op = cur;
    }
}

// ---------------- launch ------------------------------------------------------
extern "C" void kernel_launch(void* const* d_in, const int* in_sizes, int n_in,
                              void* d_out, int out_size) {
    const float* x  = (const float*)d_in[0];
    const float* ne = (const float*)d_in[1];
    const float* t  = (const float*)d_in[2];
    const float* nt = (const float*)d_in[3];
    const float* p  = (const float*)d_in[4];
    const float* wp = (const float*)d_in[5];
    const float* bp = (const float*)d_in[6];
    float* out = (float*)d_out;

    float *y1, *y2, *csx, *csy;
    cudaGetSymbolAddress((void**)&y1, g_y1);
    cudaGetSymbolAddress((void**)&y2, g_y2);
    cudaGetSymbolAddress((void**)&csx, g_csx);
    cudaGetSymbolAddress((void**)&csy, g_csy);

    k_prep<<<BSZ, 64>>>(t, nt, p, wp, bp);
    k_colsum<<<BSZ, 256>>>(x, csx);
    k_wn<<<dim3(128, 24), 256>>>(ne, wp);
    k_select<<<NN, 256>>>(ne);
    k_spmv<<<4096, 256>>>(x, csx, x, y1, 0);
    k_colsum<<<BSZ, 256>>>(y1, csy);
    k_spmv<<<4096, 256>>>(y1, csy, x, y2, 1);
    k_out1<<<NN, 128>>>(x, y1, y2, ne, bp, out);
    k_out2<<<dim3(32, BSZ), 256>>>(x, y1, y2, out);
}